// round 7
// baseline (speedup 1.0000x reference)
#include <cuda_runtime.h>
#include <cuda_fp16.h>
#include <math.h>
#include <stdint.h>

#define SEQ 8192
#define DM 1024
#define NH 16
#define DH 64
#define NN (NH*DH)   // 1024

#define KTOT 1024
#define KSTAGE 64                  // halves per panel row (128B)
#define NSTG 3
#define NKT (KTOT/KSTAGE)          // 16 panels
#define STG_BYTES 32768            // A tile 16KB + B tile 16KB
#define SMEM_BYTES (NSTG*STG_BYTES)  // 98304

// ---------------- scratch ----------------
__device__ __half g_xs_h[SEQ * DM];
__device__ __half g_wk_h[NN * DM];
__device__ __half g_wv_h[NN * DM];
__device__ __half g_w1_h[DM * NN];
__device__ __half g_w2_h[NN * DM];
__device__ __half g_attn_h[SEQ * NN];
__device__ __half g_h1_h[SEQ * DM];
__device__ __half g_v_h[SEQ * NN];   // v projection, fp16
__device__ float g_a   [SEQ * NH];
__device__ float g_pa  [64 * NH];    // per-chunk sums of a
__device__ float g_pav [64 * NN];
__device__ float g_bav [64 * NN];
__device__ float g_basea[64 * NH];

__device__ __forceinline__ uint32_t smem_u32(const void* p) {
    uint32_t a;
    asm("{ .reg .u64 t; cvta.to.shared.u64 t, %1; cvt.u32.u64 %0, t; }" : "=r"(a) : "l"(p));
    return a;
}

// one stage: 16 x 16B cp.async per thread (128 threads fill 32KB)
__device__ __forceinline__ void load_stage(uint32_t sb, int s, int kt,
                                           const __half* gA, const __half* gB,
                                           const uint32_t* doff)
{
    const uint32_t ab = sb + s * STG_BYTES;
    const uint32_t bb = ab + 16384;
    const __half* a = gA + kt * KSTAGE;
    const __half* b = gB + kt * KSTAGE;
#pragma unroll
    for (int i = 0; i < 8; i++) {
        asm volatile("cp.async.cg.shared.global [%0], [%1], 16;"
                     :: "r"(ab + doff[i]), "l"(a + i * 8) : "memory");
        asm volatile("cp.async.cg.shared.global [%0], [%1], 16;"
                     :: "r"(bb + doff[i]), "l"(b + i * 8) : "memory");
    }
    asm volatile("cp.async.commit_group;" ::: "memory");
}

// ---------------------------------------------------------------------------
// GEMM core: 128x128 CTA tile, 4 warps (2x2) each 64x64, cp.async 3-stage,
// ldmatrix + m16n8k16 fp16 with f32 accumulate. acc[i][j][q]: i = A 16-row
// block, j = B 8-col block (0..7), q = mma fragment element.
// ---------------------------------------------------------------------------
__device__ __forceinline__ void gemm_core(const __half* __restrict__ A,
                                          const __half* __restrict__ B,
                                          int bm, int bn, char* smem_raw,
                                          float (&acc)[4][8][4])
{
    const uint32_t sb = smem_u32(smem_raw);
    const int tid = threadIdx.x, lane = tid & 31, wid = tid >> 5;
    const int warp_m = (wid & 1) * 64;
    const int warp_n = (wid >> 1) * 64;

    // cp.async mapping: thread -> row tid, all 8 chunks of that row
    const __half* gA = A + (size_t)(bm * 128 + tid) * KTOT;
    const __half* gB = B + (size_t)(bn * 128 + tid) * KTOT;
    uint32_t doff[8];
#pragma unroll
    for (int i = 0; i < 8; i++)
        doff[i] = tid * 128 + ((i ^ (tid & 7)) << 4);

    // ldmatrix lane bases
    const int rbase = (lane & 7) + ((lane >> 3) & 1) * 8;
    const int klane = lane >> 4;
    const int rA_base = warp_m + rbase;
    const int rB_base = warp_n + rbase;

#pragma unroll
    for (int i = 0; i < 4; i++)
#pragma unroll
        for (int j = 0; j < 8; j++)
#pragma unroll
            for (int q = 0; q < 4; q++) acc[i][j][q] = 0.f;

    load_stage(sb, 0, 0, gA, gB, doff);
    load_stage(sb, 1, 1, gA, gB, doff);

    for (int kt = 0; kt < NKT; kt++) {
        if (kt + 1 < NKT) asm volatile("cp.async.wait_group 1;" ::: "memory");
        else              asm volatile("cp.async.wait_group 0;" ::: "memory");
        __syncthreads();
        if (kt + 2 < NKT) load_stage(sb, (kt + 2) % NSTG, kt + 2, gA, gB, doff);

        const uint32_t ab = sb + (kt % NSTG) * STG_BYTES;
        const uint32_t bb = ab + 16384;

#pragma unroll
        for (int kg = 0; kg < 4; kg++) {
            const int kc = 2 * kg + klane;
            uint32_t bfr[16];
#pragma unroll
            for (int p = 0; p < 4; p++) {
                const int row = rB_base + 16 * p;
                uint32_t addr = bb + (uint32_t)row * 128 + (uint32_t)((kc ^ (row & 7)) << 4);
                asm volatile("ldmatrix.sync.aligned.m8n8.x4.shared.b16 {%0,%1,%2,%3}, [%4];"
                    : "=r"(bfr[4*p]), "=r"(bfr[4*p+1]), "=r"(bfr[4*p+2]), "=r"(bfr[4*p+3])
                    : "r"(addr));
            }
#pragma unroll
            for (int i = 0; i < 4; i++) {
                const int row = rA_base + 16 * i;
                uint32_t af[4];
                uint32_t addr = ab + (uint32_t)row * 128 + (uint32_t)((kc ^ (row & 7)) << 4);
                asm volatile("ldmatrix.sync.aligned.m8n8.x4.shared.b16 {%0,%1,%2,%3}, [%4];"
                    : "=r"(af[0]), "=r"(af[1]), "=r"(af[2]), "=r"(af[3]) : "r"(addr));
#pragma unroll
                for (int j = 0; j < 8; j++) {
                    const int bi = (j >> 1) * 4 + (j & 1);
                    asm volatile(
                        "mma.sync.aligned.m16n8k16.row.col.f32.f16.f16.f32 "
                        "{%0,%1,%2,%3}, {%4,%5,%6,%7}, {%8,%9}, {%0,%1,%2,%3};"
                        : "+f"(acc[i][j][0]), "+f"(acc[i][j][1]),
                          "+f"(acc[i][j][2]), "+f"(acc[i][j][3])
                        : "r"(af[0]), "r"(af[1]), "r"(af[2]), "r"(af[3]),
                          "r"(bfr[bi]), "r"(bfr[bi + 2]));
                }
            }
        }
    }
}

// ---------------------------------------------------------------------------
// Fused K+V projection: grid (16, 64). bn<8 -> k-proj (elu+1, per-head sum
// into g_a); bn>=8 -> v-proj (fp16 store).
// ---------------------------------------------------------------------------
__global__ __launch_bounds__(128, 2)
void gemm_kv(const __half* __restrict__ xs, const __half* __restrict__ wk,
             const __half* __restrict__ wv)
{
    extern __shared__ char smem[];
    const int bm = blockIdx.y;
    const bool is_k = blockIdx.x < 8;
    const int bn = blockIdx.x & 7;
    const __half* B = is_k ? wk : wv;

    float acc[4][8][4];
    gemm_core(xs, B, bm, bn, smem, acc);

    const int tid = threadIdx.x, lane = tid & 31, wid = tid >> 5;
    const int warp_m = (wid & 1) * 64;
    const int warp_n = (wid >> 1) * 64;
    const int g = lane >> 2, tig = lane & 3;

    if (is_k) {
        // warp's 64 cols = one full head: head = bn*2 + (warp_n>>6)
        const int head = bn * 2 + (warp_n >> 6);
#pragma unroll
        for (int i = 0; i < 4; i++) {
#pragma unroll
            for (int half = 0; half < 2; half++) {
                float s = 0.f;
#pragma unroll
                for (int j = 0; j < 8; j++) {
                    float x0 = acc[i][j][2 * half + 0];
                    float x1 = acc[i][j][2 * half + 1];
                    s += (x0 > 0.f) ? (x0 + 1.f) : expf(x0);
                    s += (x1 > 0.f) ? (x1 + 1.f) : expf(x1);
                }
                s += __shfl_xor_sync(0xFFFFFFFFu, s, 1);
                s += __shfl_xor_sync(0xFFFFFFFFu, s, 2);
                if (tig == 0) {
                    int row = bm * 128 + warp_m + 16 * i + 8 * half + g;
                    g_a[(size_t)row * NH + head] = s;
                }
            }
        }
    } else {
#pragma unroll
        for (int i = 0; i < 4; i++) {
            int row0 = bm * 128 + warp_m + 16 * i + g;
#pragma unroll
            for (int j = 0; j < 8; j++) {
                int colg = bn * 128 + warp_n + 8 * j + 2 * tig;
#pragma unroll
                for (int half = 0; half < 2; half++) {
                    int row = row0 + 8 * half;
                    __half2 o = __floats2half2_rn(acc[i][j][2 * half], acc[i][j][2 * half + 1]);
                    *(__half2*)(g_v_h + (size_t)row * 1024 + colg) = o;
                }
            }
        }
    }
}

// ---------------------------------------------------------------------------
// MLP GEMMs. EPI: 2 = gelu(x+b)->fp16, 3 = x+b->f32
// ---------------------------------------------------------------------------
template<int EPI>
__global__ __launch_bounds__(128, 2)
void gemm_h(const __half* __restrict__ A, const __half* __restrict__ B,
            const float* __restrict__ bias, void* __restrict__ Cv)
{
    extern __shared__ char smem[];
    const int bm = blockIdx.y, bn = blockIdx.x;

    float acc[4][8][4];
    gemm_core(A, B, bm, bn, smem, acc);

    const int tid = threadIdx.x, lane = tid & 31, wid = tid >> 5;
    const int warp_m = (wid & 1) * 64;
    const int warp_n = (wid >> 1) * 64;
    const int g = lane >> 2, tig = lane & 3;

#pragma unroll
    for (int i = 0; i < 4; i++) {
        int row0 = bm * 128 + warp_m + 16 * i + g;
#pragma unroll
        for (int j = 0; j < 8; j++) {
            int colg = bn * 128 + warp_n + 8 * j + 2 * tig;
            float bia0 = bias[colg], bia1 = bias[colg + 1];
#pragma unroll
            for (int half = 0; half < 2; half++) {
                int row = row0 + 8 * half;
                float x0 = acc[i][j][2 * half + 0] + bia0;
                float x1 = acc[i][j][2 * half + 1] + bia1;
                if (EPI == 2) {
                    float t0 = 0.7978845608028654f * (x0 + 0.044715f * x0 * x0 * x0);
                    float t1 = 0.7978845608028654f * (x1 + 0.044715f * x1 * x1 * x1);
                    x0 = 0.5f * x0 * (1.f + tanhf(t0));
                    x1 = 0.5f * x1 * (1.f + tanhf(t1));
                    __half2 o = __floats2half2_rn(x0, x1);
                    *(__half2*)((__half*)Cv + (size_t)row * 1024 + colg) = o;
                } else {
                    float2 o = make_float2(x0, x1);
                    *(float2*)((float*)Cv + (size_t)row * 1024 + colg) = o;
                }
            }
        }
    }
}

// ---------------------------------------------------------------------------
// f32 -> fp16 conversion, ILP=4 grid-stride
__global__ void conv_xs(const float4* __restrict__ src, __half2* __restrict__ dst, int n4)
{
    const int stride = gridDim.x * blockDim.x;
    int i = blockIdx.x * blockDim.x + threadIdx.x;
#pragma unroll
    for (int k = 0; k < 4; k++) {
        int idx = i + k * stride;
        if (idx < n4) {
            float4 v = src[idx];
            dst[2 * idx]     = __floats2half2_rn(v.x, v.y);
            dst[2 * idx + 1] = __floats2half2_rn(v.z, v.w);
        }
    }
}

__global__ void conv_w(const float4* __restrict__ s0, __half2* __restrict__ d0,
                       const float4* __restrict__ s1, __half2* __restrict__ d1,
                       const float4* __restrict__ s2, __half2* __restrict__ d2,
                       const float4* __restrict__ s3, __half2* __restrict__ d3)
{
    const int SEG = 262144;
    const int stride = gridDim.x * blockDim.x;
    int i = blockIdx.x * blockDim.x + threadIdx.x;
#pragma unroll
    for (int k = 0; k < 4; k++) {
        int idx = i + k * stride;
        if (idx >= 4 * SEG) continue;
        const float4* s; __half2* d;
        int seg = idx >> 18, off = idx & (SEG - 1);
        if (seg == 0) { s = s0; d = d0; }
        else if (seg == 1) { s = s1; d = d1; }
        else if (seg == 2) { s = s2; d = d2; }
        else { s = s3; d = d3; }
        float4 v = s[off];
        d[2 * off]     = __floats2half2_rn(v.x, v.y);
        d[2 * off + 1] = __floats2half2_rn(v.z, v.w);
    }
}

// ---- chunked scans: 64 chunks of 128 steps ----
// pass1: per-chunk sums of a*v, plus per-chunk sums of a (fused)
__global__ void scan_pass1()
{
    const int c = blockIdx.x, h = blockIdx.y, v = threadIdx.x;
    __shared__ float a_s[128];
    __shared__ float wsum[2];
    a_s[v]      = g_a[(c * 128 + v) * NH + h];
    a_s[v + 64] = g_a[(c * 128 + v + 64) * NH + h];
    __syncthreads();

    // chunk sum of a (fused former pass2a heavy read)
    float s = a_s[v] + a_s[v + 64];
#pragma unroll
    for (int off = 16; off > 0; off >>= 1)
        s += __shfl_xor_sync(0xFFFFFFFFu, s, off);
    if ((v & 31) == 0) wsum[v >> 5] = s;

    const int hv = h * DH + v;
    float acc = 0.f;
#pragma unroll 4
    for (int t = 0; t < 128; t++)
        acc = fmaf(a_s[t], __half2float(g_v_h[(size_t)(c * 128 + t) * NN + hv]), acc);
    g_pav[c * NN + hv] = acc;

    __syncthreads();
    if (v == 0) g_pa[c * NH + h] = wsum[0] + wsum[1];
}

// tiny: exclusive scan of per-chunk a sums
__global__ void scan_pass2a()
{
    const int h = threadIdx.x;
    if (h >= NH) return;
    float acc = 0.f;
    for (int c = 0; c < 64; c++) {
        float x = g_pa[c * NH + h];
        g_basea[c * NH + h] = acc;
        acc += x;
    }
}

__global__ void scan_pass2c()
{
    const int hv = blockIdx.x * blockDim.x + threadIdx.x;
    float acc = 0.f;
    for (int c = 0; c < 64; c++) {
        float x = g_pav[c * NN + hv];
        g_bav[c * NN + hv] = acc;
        acc += x;
    }
}

__global__ void scan_pass3()
{
    const int c = blockIdx.x, h = blockIdx.y, v = threadIdx.x;
    __shared__ float a_s[128];
    __shared__ float inv_s[128];
    a_s[v]      = g_a[(c * 128 + v) * NH + h];
    a_s[v + 64] = g_a[(c * 128 + v + 64) * NH + h];
    __syncthreads();
    if (v == 0) {
        float run = g_basea[c * NH + h];
        for (int t = 0; t < 128; t++) { run += a_s[t]; inv_s[t] = run; }
    }
    __syncthreads();
    inv_s[v]      = 1.0f / inv_s[v];
    inv_s[v + 64] = 1.0f / inv_s[v + 64];
    __syncthreads();

    const int hv = h * DH + v;
    float acc = g_bav[c * NN + hv];
#pragma unroll 4
    for (int t = 0; t < 128; t++) {
        acc = fmaf(a_s[t], __half2float(g_v_h[(size_t)(c * 128 + t) * NN + hv]), acc);
        g_attn_h[(size_t)(c * 128 + t) * NN + hv] = __float2half_rn(acc * inv_s[t]);
    }
}

// ---------------------------------------------------------------------------
extern "C" void kernel_launch(void* const* d_in, const int* in_sizes, int n_in,
                              void* d_out, int out_size)
{
    const float* xs = (const float*)d_in[0];
    // d_in[1] = wq: unused (query factor cancels in sq/zq)
    const float* wk = (const float*)d_in[2];
    const float* wv = (const float*)d_in[3];
    const float* w1 = (const float*)d_in[4];
    const float* b1 = (const float*)d_in[5];
    const float* w2 = (const float*)d_in[6];
    const float* b2 = (const float*)d_in[7];
    float* out = (float*)d_out;

    __half *xs_h, *wk_h, *wv_h, *w1_h, *w2_h, *attn_h, *h1_h;
    cudaGetSymbolAddress((void**)&xs_h, g_xs_h);
    cudaGetSymbolAddress((void**)&wk_h, g_wk_h);
    cudaGetSymbolAddress((void**)&wv_h, g_wv_h);
    cudaGetSymbolAddress((void**)&w1_h, g_w1_h);
    cudaGetSymbolAddress((void**)&w2_h, g_w2_h);
    cudaGetSymbolAddress((void**)&attn_h, g_attn_h);
    cudaGetSymbolAddress((void**)&h1_h, g_h1_h);

    cudaFuncSetAttribute(gemm_kv,   cudaFuncAttributeMaxDynamicSharedMemorySize, SMEM_BYTES);
    cudaFuncSetAttribute(gemm_h<2>, cudaFuncAttributeMaxDynamicSharedMemorySize, SMEM_BYTES);
    cudaFuncSetAttribute(gemm_h<3>, cudaFuncAttributeMaxDynamicSharedMemorySize, SMEM_BYTES);

    {
        int n4 = SEQ * DM / 4;
        conv_xs<<<n4 / (256 * 4), 256>>>((const float4*)xs, (__half2*)xs_h, n4);
        conv_w<<<(4 * 262144) / (256 * 4), 256>>>(
            (const float4*)wk, (__half2*)wk_h, (const float4*)wv, (__half2*)wv_h,
            (const float4*)w1, (__half2*)w1_h, (const float4*)w2, (__half2*)w2_h);
    }

    // fused k+v projection
    gemm_kv<<<dim3(16, 64), 128, SMEM_BYTES>>>(xs_h, wk_h, wv_h);

    // linear-attention chunked scan
    scan_pass1<<<dim3(64, NH), DH>>>();
    scan_pass2a<<<1, 32>>>();
    scan_pass2c<<<4, 256>>>();
    scan_pass3<<<dim3(64, NH), DH>>>();

    // MLP
    gemm_h<2><<<dim3(8, 64), 128, SMEM_BYTES>>>(attn_h, w1_h, b1, h1_h);
    gemm_h<3><<<dim3(8, 64), 128, SMEM_BYTES>>>(h1_h, w2_h, b2, out);
}

// round 8
// speedup vs baseline: 1.4208x; 1.4208x over previous
#include <cuda_runtime.h>
#include <cuda_fp16.h>
#include <math.h>
#include <stdint.h>

#define SEQ 8192
#define DM 1024
#define NH 16
#define DH 64
#define NN (NH*DH)   // 1024

#define KTOT 1024
#define KSTAGE 64                  // halves per panel row (128B)
#define NSTG 3
#define NKT (KTOT/KSTAGE)          // 16 panels
#define STG_BYTES 32768            // A tile 16KB + B tile 16KB
#define SMEM_BYTES (NSTG*STG_BYTES)  // 98304

#define NC 128                     // scan chunks
#define CH 64                      // steps per chunk

// ---------------- scratch ----------------
__device__ __half g_xs_h[SEQ * DM];
__device__ __half g_wk_h[NN * DM];
__device__ __half g_wv_h[NN * DM];
__device__ __half g_w1_h[DM * NN];
__device__ __half g_w2_h[NN * DM];
__device__ __half g_attn_h[SEQ * NN];
__device__ __half g_h1_h[SEQ * DM];
__device__ __half g_v_h[SEQ * NN];   // v projection, fp16
__device__ float g_a   [SEQ * NH];
__device__ float g_pa  [NC * NH];    // per-chunk sums of a
__device__ float g_pav [NC * NN];    // per-chunk sums of a*v
__device__ float g_bav [NC * NN];    // exclusive chunk bases of a*v
__device__ float g_basea[NC * NH];   // exclusive chunk bases of a

__device__ __forceinline__ uint32_t smem_u32(const void* p) {
    uint32_t a;
    asm("{ .reg .u64 t; cvta.to.shared.u64 t, %1; cvt.u32.u64 %0, t; }" : "=r"(a) : "l"(p));
    return a;
}

// one stage: 8 x 16B cp.async per thread (256 threads fill 32KB)
__device__ __forceinline__ void load_stage(uint32_t sb, int s, int kt,
                                           const __half* gA, const __half* gB,
                                           const uint32_t* doff)
{
    const uint32_t ab = sb + s * STG_BYTES;
    const uint32_t bb = ab + 16384;
    const __half* a = gA + kt * KSTAGE;
    const __half* b = gB + kt * KSTAGE;
#pragma unroll
    for (int i = 0; i < 4; i++) {
        asm volatile("cp.async.cg.shared.global [%0], [%1], 16;"
                     :: "r"(ab + doff[i]), "l"(a + i * 8) : "memory");
        asm volatile("cp.async.cg.shared.global [%0], [%1], 16;"
                     :: "r"(bb + doff[i]), "l"(b + i * 8) : "memory");
    }
    asm volatile("cp.async.commit_group;" ::: "memory");
}

// ---------------------------------------------------------------------------
// GEMM core (round-6 proven): 128x128 CTA, 8 warps (2x4) of 64x32,
// cp.async 3-stage, ldmatrix, m16n8k16 fp16 -> f32.
// ---------------------------------------------------------------------------
__device__ __forceinline__ void gemm_core(const __half* __restrict__ A,
                                          const __half* __restrict__ B,
                                          int bm, int bn, float* smf,
                                          float (&acc)[4][4][4])
{
    const uint32_t sb = smem_u32(smf);
    const int tid = threadIdx.x, lane = tid & 31, wid = tid >> 5;
    const int warp_m = (wid >> 2) * 64;
    const int warp_n = (wid & 3) * 32;

    const int crow = tid >> 1;
    const int cc0 = (tid & 1) * 4;
    const __half* gA = A + (size_t)(bm * 128 + crow) * KTOT + cc0 * 8;
    const __half* gB = B + (size_t)(bn * 128 + crow) * KTOT + cc0 * 8;
    uint32_t doff[4];
#pragma unroll
    for (int i = 0; i < 4; i++)
        doff[i] = crow * 128 + (((cc0 + i) ^ (crow & 7)) << 4);

    const int rbase = (lane & 7) + ((lane >> 3) & 1) * 8;
    const int klane = lane >> 4;
    const int rA_base = warp_m + rbase;
    const int rB_base = warp_n + rbase;

#pragma unroll
    for (int i = 0; i < 4; i++)
#pragma unroll
        for (int j = 0; j < 4; j++)
#pragma unroll
            for (int q = 0; q < 4; q++) acc[i][j][q] = 0.f;

    load_stage(sb, 0, 0, gA, gB, doff);
    load_stage(sb, 1, 1, gA, gB, doff);

    for (int kt = 0; kt < NKT; kt++) {
        if (kt + 1 < NKT) asm volatile("cp.async.wait_group 1;" ::: "memory");
        else              asm volatile("cp.async.wait_group 0;" ::: "memory");
        __syncthreads();
        if (kt + 2 < NKT) load_stage(sb, (kt + 2) % NSTG, kt + 2, gA, gB, doff);

        const uint32_t ab = sb + (kt % NSTG) * STG_BYTES;
        const uint32_t bb = ab + 16384;

#pragma unroll
        for (int kg = 0; kg < 4; kg++) {
            const int kc = 2 * kg + klane;
            uint32_t bfr[8];
#pragma unroll
            for (int p = 0; p < 2; p++) {
                const int row = rB_base + 16 * p;
                uint32_t addr = bb + (uint32_t)row * 128 + (uint32_t)((kc ^ (row & 7)) << 4);
                asm volatile("ldmatrix.sync.aligned.m8n8.x4.shared.b16 {%0,%1,%2,%3}, [%4];"
                    : "=r"(bfr[4*p]), "=r"(bfr[4*p+1]), "=r"(bfr[4*p+2]), "=r"(bfr[4*p+3])
                    : "r"(addr));
            }
#pragma unroll
            for (int i = 0; i < 4; i++) {
                const int row = rA_base + 16 * i;
                uint32_t af[4];
                uint32_t addr = ab + (uint32_t)row * 128 + (uint32_t)((kc ^ (row & 7)) << 4);
                asm volatile("ldmatrix.sync.aligned.m8n8.x4.shared.b16 {%0,%1,%2,%3}, [%4];"
                    : "=r"(af[0]), "=r"(af[1]), "=r"(af[2]), "=r"(af[3]) : "r"(addr));
#pragma unroll
                for (int j = 0; j < 4; j++) {
                    const int bi = (j >> 1) * 4 + (j & 1);
                    asm volatile(
                        "mma.sync.aligned.m16n8k16.row.col.f32.f16.f16.f32 "
                        "{%0,%1,%2,%3}, {%4,%5,%6,%7}, {%8,%9}, {%0,%1,%2,%3};"
                        : "+f"(acc[i][j][0]), "+f"(acc[i][j][1]),
                          "+f"(acc[i][j][2]), "+f"(acc[i][j][3])
                        : "r"(af[0]), "r"(af[1]), "r"(af[2]), "r"(af[3]),
                          "r"(bfr[bi]), "r"(bfr[bi + 2]));
                }
            }
        }
    }
}

// ---------------------------------------------------------------------------
// Fused K+V projection (one launch, grid (16,64)):
// bn<8 -> k-proj: elu+1, per-head 64-col reduce -> g_a; else v-proj -> fp16.
// ---------------------------------------------------------------------------
__global__ __launch_bounds__(256, 2)
void gemm_kv(const __half* __restrict__ xs, const __half* __restrict__ wk,
             const __half* __restrict__ wv)
{
    extern __shared__ float smf[];
    const int bm = blockIdx.y;
    const bool is_k = blockIdx.x < 8;
    const int bn = blockIdx.x & 7;

    float acc[4][4][4];
    gemm_core(xs, is_k ? wk : wv, bm, bn, smf, acc);

    const int tid = threadIdx.x, lane = tid & 31, wid = tid >> 5;
    const int warp_m = (wid >> 2) * 64;
    const int warp_n = (wid & 3) * 32;
    const int g = lane >> 2, tig = lane & 3;

    if (is_k) {
        // fused act + per-head reduction (red in stage-1 smem; last panel reads stage 0)
        float* red = smf + 8192;   // [128 rows][4 warp_n groups]
#pragma unroll
        for (int i = 0; i < 4; i++) {
#pragma unroll
            for (int half = 0; half < 2; half++) {
                float s = 0.f;
#pragma unroll
                for (int j = 0; j < 4; j++) {
                    float x0 = acc[i][j][2 * half + 0];
                    float x1 = acc[i][j][2 * half + 1];
                    s += (x0 > 0.f) ? (x0 + 1.f) : expf(x0);
                    s += (x1 > 0.f) ? (x1 + 1.f) : expf(x1);
                }
                s += __shfl_xor_sync(0xFFFFFFFFu, s, 1);
                s += __shfl_xor_sync(0xFFFFFFFFu, s, 2);
                if (tig == 0)
                    red[(warp_m + 16 * i + 8 * half + g) * 4 + (wid & 3)] = s;
            }
        }
        __syncthreads();
        {
            const int row = tid >> 1, hsel = tid & 1;
            float s = red[row * 4 + 2 * hsel] + red[row * 4 + 2 * hsel + 1];
            g_a[(size_t)(bm * 128 + row) * NH + bn * 2 + hsel] = s;
        }
    } else {
#pragma unroll
        for (int i = 0; i < 4; i++) {
            int row0 = bm * 128 + warp_m + 16 * i + g;
#pragma unroll
            for (int j = 0; j < 4; j++) {
                int colg = bn * 128 + warp_n + 8 * j + 2 * tig;
#pragma unroll
                for (int half = 0; half < 2; half++) {
                    int row = row0 + 8 * half;
                    __half2 o = __floats2half2_rn(acc[i][j][2 * half], acc[i][j][2 * half + 1]);
                    *(__half2*)(g_v_h + (size_t)row * 1024 + colg) = o;
                }
            }
        }
    }
}

// ---------------------------------------------------------------------------
// MLP GEMMs. EPI: 2 = gelu(x+b)->fp16, 3 = x+b->f32
// ---------------------------------------------------------------------------
template<int EPI>
__global__ __launch_bounds__(256, 2)
void gemm_h(const __half* __restrict__ A, const __half* __restrict__ B,
            const float* __restrict__ bias, void* __restrict__ Cv)
{
    extern __shared__ float smf[];
    const int bm = blockIdx.y, bn = blockIdx.x;

    float acc[4][4][4];
    gemm_core(A, B, bm, bn, smf, acc);

    const int tid = threadIdx.x, lane = tid & 31, wid = tid >> 5;
    const int warp_m = (wid >> 2) * 64;
    const int warp_n = (wid & 3) * 32;
    const int g = lane >> 2, tig = lane & 3;

#pragma unroll
    for (int i = 0; i < 4; i++) {
        int row0 = bm * 128 + warp_m + 16 * i + g;
#pragma unroll
        for (int j = 0; j < 4; j++) {
            int colg = bn * 128 + warp_n + 8 * j + 2 * tig;
            float bia0 = bias[colg], bia1 = bias[colg + 1];
#pragma unroll
            for (int half = 0; half < 2; half++) {
                int row = row0 + 8 * half;
                float x0 = acc[i][j][2 * half + 0] + bia0;
                float x1 = acc[i][j][2 * half + 1] + bia1;
                if (EPI == 2) {
                    float t0 = 0.7978845608028654f * (x0 + 0.044715f * x0 * x0 * x0);
                    float t1 = 0.7978845608028654f * (x1 + 0.044715f * x1 * x1 * x1);
                    x0 = 0.5f * x0 * (1.f + tanhf(t0));
                    x1 = 0.5f * x1 * (1.f + tanhf(t1));
                    __half2 o = __floats2half2_rn(x0, x1);
                    *(__half2*)((__half*)Cv + (size_t)row * 1024 + colg) = o;
                } else {
                    float2 o = make_float2(x0, x1);
                    *(float2*)((float*)Cv + (size_t)row * 1024 + colg) = o;
                }
            }
        }
    }
}

// ---------------------------------------------------------------------------
// f32 -> fp16 conversions
__global__ void conv_xs(const float4* __restrict__ src, __half2* __restrict__ dst, int n4)
{
    const int stride = gridDim.x * blockDim.x;
    int i = blockIdx.x * blockDim.x + threadIdx.x;
#pragma unroll
    for (int k = 0; k < 4; k++) {
        int idx = i + k * stride;
        if (idx < n4) {
            float4 v = src[idx];
            dst[2 * idx]     = __floats2half2_rn(v.x, v.y);
            dst[2 * idx + 1] = __floats2half2_rn(v.z, v.w);
        }
    }
}

__global__ void conv_w(const float4* __restrict__ s0, __half2* __restrict__ d0,
                       const float4* __restrict__ s1, __half2* __restrict__ d1,
                       const float4* __restrict__ s2, __half2* __restrict__ d2,
                       const float4* __restrict__ s3, __half2* __restrict__ d3)
{
    const int SEG = 262144;
    const int stride = gridDim.x * blockDim.x;
    int i = blockIdx.x * blockDim.x + threadIdx.x;
#pragma unroll
    for (int k = 0; k < 4; k++) {
        int idx = i + k * stride;
        if (idx >= 4 * SEG) continue;
        const float4* s; __half2* d;
        int seg = idx >> 18, off = idx & (SEG - 1);
        if (seg == 0) { s = s0; d = d0; }
        else if (seg == 1) { s = s1; d = d1; }
        else if (seg == 2) { s = s2; d = d2; }
        else { s = s3; d = d3; }
        float4 v = s[off];
        d[2 * off]     = __floats2half2_rn(v.x, v.y);
        d[2 * off + 1] = __floats2half2_rn(v.z, v.w);
    }
}

// ---- chunked scans: NC=128 chunks of CH=64 steps ----
// pass1: per-chunk sums of a*v + per-chunk sums of a
__global__ void scan_pass1()
{
    const int c = blockIdx.x, h = blockIdx.y, v = threadIdx.x;
    __shared__ float a_s[CH];
    __shared__ float wsum[2];
    a_s[v] = g_a[(c * CH + v) * NH + h];
    __syncthreads();

    float s = a_s[v];
#pragma unroll
    for (int off = 16; off > 0; off >>= 1)
        s += __shfl_xor_sync(0xFFFFFFFFu, s, off);
    if ((v & 31) == 0) wsum[v >> 5] = s;

    const int hv = h * DH + v;
    float acc = 0.f;
#pragma unroll 4
    for (int t = 0; t < CH; t++)
        acc = fmaf(a_s[t], __half2float(g_v_h[(size_t)(c * CH + t) * NN + hv]), acc);
    g_pav[c * NN + hv] = acc;

    __syncthreads();
    if (v == 0) g_pa[c * NH + h] = wsum[0] + wsum[1];
}

// exclusive scan over chunks of per-chunk a sums (tiny)
__global__ void scan_pass2a()
{
    const int h = threadIdx.x;
    if (h >= NH) return;
    float acc = 0.f;
    for (int c = 0; c < NC; c++) {
        float x = g_pa[c * NH + h];
        g_basea[c * NH + h] = acc;
        acc += x;
    }
}

// exclusive scan of pav over chunks: one block of 128 threads per hv (Hillis-Steele)
__global__ void scan_pass2c()
{
    const int hv = blockIdx.x, t = threadIdx.x;
    __shared__ float s[NC];
    float orig = g_pav[t * NN + hv];
    s[t] = orig;
    __syncthreads();
#pragma unroll
    for (int off = 1; off < NC; off <<= 1) {
        float x = (t >= off) ? s[t - off] : 0.f;
        __syncthreads();
        s[t] += x;
        __syncthreads();
    }
    g_bav[t * NN + hv] = s[t] - orig;
}

// pass3: within-chunk scan + normalize -> fp16 attn
__global__ void scan_pass3()
{
    const int c = blockIdx.x, h = blockIdx.y, v = threadIdx.x;
    __shared__ float a_s[CH];
    __shared__ float sc[CH];
    a_s[v] = g_a[(c * CH + v) * NH + h];
    sc[v] = a_s[v];
    __syncthreads();
    // inclusive Hillis-Steele scan of a over the chunk
#pragma unroll
    for (int off = 1; off < CH; off <<= 1) {
        float x = (v >= off) ? sc[v - off] : 0.f;
        __syncthreads();
        sc[v] += x;
        __syncthreads();
    }
    __shared__ float inv_s[CH];
    inv_s[v] = 1.0f / (g_basea[c * NH + h] + sc[v]);
    __syncthreads();

    const int hv = h * DH + v;
    float acc = g_bav[c * NN + hv];
#pragma unroll 4
    for (int t = 0; t < CH; t++) {
        acc = fmaf(a_s[t], __half2float(g_v_h[(size_t)(c * CH + t) * NN + hv]), acc);
        g_attn_h[(size_t)(c * CH + t) * NN + hv] = __float2half_rn(acc * inv_s[t]);
    }
}

// ---------------------------------------------------------------------------
extern "C" void kernel_launch(void* const* d_in, const int* in_sizes, int n_in,
                              void* d_out, int out_size)
{
    const float* xs = (const float*)d_in[0];
    // d_in[1] = wq: unused (query factor cancels in sq/zq)
    const float* wk = (const float*)d_in[2];
    const float* wv = (const float*)d_in[3];
    const float* w1 = (const float*)d_in[4];
    const float* b1 = (const float*)d_in[5];
    const float* w2 = (const float*)d_in[6];
    const float* b2 = (const float*)d_in[7];
    float* out = (float*)d_out;

    __half *xs_h, *wk_h, *wv_h, *w1_h, *w2_h, *attn_h, *h1_h;
    cudaGetSymbolAddress((void**)&xs_h, g_xs_h);
    cudaGetSymbolAddress((void**)&wk_h, g_wk_h);
    cudaGetSymbolAddress((void**)&wv_h, g_wv_h);
    cudaGetSymbolAddress((void**)&w1_h, g_w1_h);
    cudaGetSymbolAddress((void**)&w2_h, g_w2_h);
    cudaGetSymbolAddress((void**)&attn_h, g_attn_h);
    cudaGetSymbolAddress((void**)&h1_h, g_h1_h);

    cudaFuncSetAttribute(gemm_kv,   cudaFuncAttributeMaxDynamicSharedMemorySize, SMEM_BYTES);
    cudaFuncSetAttribute(gemm_h<2>, cudaFuncAttributeMaxDynamicSharedMemorySize, SMEM_BYTES);
    cudaFuncSetAttribute(gemm_h<3>, cudaFuncAttributeMaxDynamicSharedMemorySize, SMEM_BYTES);

    {
        int n4 = SEQ * DM / 4;
        conv_xs<<<n4 / (256 * 4), 256>>>((const float4*)xs, (__half2*)xs_h, n4);
        conv_w<<<(4 * 262144) / (256 * 4), 256>>>(
            (const float4*)wk, (__half2*)wk_h, (const float4*)wv, (__half2*)wv_h,
            (const float4*)w1, (__half2*)w1_h, (const float4*)w2, (__half2*)w2_h);
    }

    // fused k+v projection (one launch)
    gemm_kv<<<dim3(16, 64), 256, SMEM_BYTES>>>(xs_h, wk_h, wv_h);

    // linear-attention chunked scan
    scan_pass1<<<dim3(NC, NH), CH>>>();
    scan_pass2a<<<1, 32>>>();
    scan_pass2c<<<NN, NC>>>();
    scan_pass3<<<dim3(NC, NH), CH>>>();

    // MLP
    gemm_h<2><<<dim3(8, 64), 256, SMEM_BYTES>>>(attn_h, w1_h, b1, h1_h);
    gemm_h<3><<<dim3(8, 64), 256, SMEM_BYTES>>>(h1_h, w2_h, b2, out);
}

// round 9
// speedup vs baseline: 1.4291x; 1.0058x over previous
#include <cuda_runtime.h>
#include <cuda_fp16.h>
#include <math.h>
#include <stdint.h>

#define SEQ 8192
#define DM 1024
#define NH 16
#define DH 64
#define NN (NH*DH)   // 1024

#define KTOT 1024
#define KSTAGE 64                  // halves per panel row (128B)
#define NSTG 3
#define NKT (KTOT/KSTAGE)          // 16 panels
#define STG_BYTES 32768            // A tile 16KB + B tile 16KB
#define SMEM_BYTES (NSTG*STG_BYTES)  // 98304

#define NC 128                     // scan chunks
#define CH 64                      // steps per chunk

// ---------------- scratch ----------------
__device__ __half g_xs_h[SEQ * DM];
__device__ __half g_wk_h[NN * DM];
__device__ __half g_wv_h[NN * DM];
__device__ __half g_w1_h[DM * NN];
__device__ __half g_w2_h[NN * DM];
__device__ __half g_attn_h[SEQ * NN];
__device__ __half g_h1_h[SEQ * DM];
__device__ __half g_v_h[SEQ * NN];   // v projection, fp16
__device__ float g_a   [SEQ * NH];
__device__ float g_pa  [NC * NH];    // per-chunk sums of a
__device__ float g_pav [NC * NN];    // per-chunk sums of a*v
__device__ float g_bav [NC * NN];    // exclusive chunk bases of a*v
__device__ float g_basea[NC * NH];   // exclusive chunk bases of a

__device__ __forceinline__ uint32_t smem_u32(const void* p) {
    uint32_t a;
    asm("{ .reg .u64 t; cvta.to.shared.u64 t, %1; cvt.u32.u64 %0, t; }" : "=r"(a) : "l"(p));
    return a;
}

// one stage: 8 x 16B cp.async per thread (256 threads fill 32KB)
__device__ __forceinline__ void load_stage(uint32_t sb, int s, int kt,
                                           const __half* gA, const __half* gB,
                                           const uint32_t* doff)
{
    const uint32_t ab = sb + s * STG_BYTES;
    const uint32_t bb = ab + 16384;
    const __half* a = gA + kt * KSTAGE;
    const __half* b = gB + kt * KSTAGE;
#pragma unroll
    for (int i = 0; i < 4; i++) {
        asm volatile("cp.async.cg.shared.global [%0], [%1], 16;"
                     :: "r"(ab + doff[i]), "l"(a + i * 8) : "memory");
        asm volatile("cp.async.cg.shared.global [%0], [%1], 16;"
                     :: "r"(bb + doff[i]), "l"(b + i * 8) : "memory");
    }
    asm volatile("cp.async.commit_group;" ::: "memory");
}

// fragment loaders
__device__ __forceinline__ void ldsmB(uint32_t bb, int rB_base, int kc, uint32_t* dst)
{
#pragma unroll
    for (int p = 0; p < 2; p++) {
        const int row = rB_base + 16 * p;
        uint32_t addr = bb + (uint32_t)row * 128 + (uint32_t)((kc ^ (row & 7)) << 4);
        asm volatile("ldmatrix.sync.aligned.m8n8.x4.shared.b16 {%0,%1,%2,%3}, [%4];"
            : "=r"(dst[4*p]), "=r"(dst[4*p+1]), "=r"(dst[4*p+2]), "=r"(dst[4*p+3])
            : "r"(addr));
    }
}
__device__ __forceinline__ void ldsmA(uint32_t ab, int rA_base, int kc, int i, uint32_t* dst)
{
    const int row = rA_base + 16 * i;
    uint32_t addr = ab + (uint32_t)row * 128 + (uint32_t)((kc ^ (row & 7)) << 4);
    asm volatile("ldmatrix.sync.aligned.m8n8.x4.shared.b16 {%0,%1,%2,%3}, [%4];"
        : "=r"(dst[0]), "=r"(dst[1]), "=r"(dst[2]), "=r"(dst[3]) : "r"(addr));
}

// ---------------------------------------------------------------------------
// GEMM core: 128x128 CTA, 8 warps (2x4) of 64x32, cp.async 3-stage,
// ldmatrix + m16n8k16 fp16 -> f32, fragment-level software pipelining.
// ---------------------------------------------------------------------------
__device__ __forceinline__ void gemm_core(const __half* __restrict__ A,
                                          const __half* __restrict__ B,
                                          int bm, int bn, float* smf,
                                          float (&acc)[4][4][4])
{
    const uint32_t sb = smem_u32(smf);
    const int tid = threadIdx.x, lane = tid & 31, wid = tid >> 5;
    const int warp_m = (wid >> 2) * 64;
    const int warp_n = (wid & 3) * 32;

    const int crow = tid >> 1;
    const int cc0 = (tid & 1) * 4;
    const __half* gA = A + (size_t)(bm * 128 + crow) * KTOT + cc0 * 8;
    const __half* gB = B + (size_t)(bn * 128 + crow) * KTOT + cc0 * 8;
    uint32_t doff[4];
#pragma unroll
    for (int i = 0; i < 4; i++)
        doff[i] = crow * 128 + (((cc0 + i) ^ (crow & 7)) << 4);

    const int rbase = (lane & 7) + ((lane >> 3) & 1) * 8;
    const int klane = lane >> 4;
    const int rA_base = warp_m + rbase;
    const int rB_base = warp_n + rbase;

#pragma unroll
    for (int i = 0; i < 4; i++)
#pragma unroll
        for (int j = 0; j < 4; j++)
#pragma unroll
            for (int q = 0; q < 4; q++) acc[i][j][q] = 0.f;

    load_stage(sb, 0, 0, gA, gB, doff);
    load_stage(sb, 1, 1, gA, gB, doff);

    for (int kt = 0; kt < NKT; kt++) {
        if (kt + 1 < NKT) asm volatile("cp.async.wait_group 1;" ::: "memory");
        else              asm volatile("cp.async.wait_group 0;" ::: "memory");
        __syncthreads();
        if (kt + 2 < NKT) load_stage(sb, (kt + 2) % NSTG, kt + 2, gA, gB, doff);

        const uint32_t ab = sb + (kt % NSTG) * STG_BYTES;
        const uint32_t bb = ab + 16384;

        uint32_t bfr[2][8], af[2][4];
        ldsmB(bb, rB_base, klane, bfr[0]);
        ldsmA(ab, rA_base, klane, 0, af[0]);

#pragma unroll
        for (int kg = 0; kg < 4; kg++) {
            const int kc = 2 * kg + klane;
#pragma unroll
            for (int i = 0; i < 4; i++) {
                // prefetch the fragments used after this step's MMAs
                if (i < 3) {
                    ldsmA(ab, rA_base, kc, i + 1, af[(i + 1) & 1]);
                } else if (kg < 3) {
                    ldsmB(bb, rB_base, kc + 2, bfr[(kg + 1) & 1]);
                    ldsmA(ab, rA_base, kc + 2, 0, af[0]);   // (i+1)&1 == 0
                }
                const uint32_t* ap = af[i & 1];
                const uint32_t* bp = bfr[kg & 1];
#pragma unroll
                for (int j = 0; j < 4; j++) {
                    const int bi = (j >> 1) * 4 + (j & 1);
                    asm volatile(
                        "mma.sync.aligned.m16n8k16.row.col.f32.f16.f16.f32 "
                        "{%0,%1,%2,%3}, {%4,%5,%6,%7}, {%8,%9}, {%0,%1,%2,%3};"
                        : "+f"(acc[i][j][0]), "+f"(acc[i][j][1]),
                          "+f"(acc[i][j][2]), "+f"(acc[i][j][3])
                        : "r"(ap[0]), "r"(ap[1]), "r"(ap[2]), "r"(ap[3]),
                          "r"(bp[bi]), "r"(bp[bi + 2]));
                }
            }
        }
    }
}

// ---------------------------------------------------------------------------
// Fused K+V projection (one launch, grid (16,64)):
// bn<8 -> k-proj: elu+1, per-head 64-col reduce -> g_a; else v-proj -> fp16.
// ---------------------------------------------------------------------------
__global__ __launch_bounds__(256, 2)
void gemm_kv(const __half* __restrict__ xs, const __half* __restrict__ wk,
             const __half* __restrict__ wv)
{
    extern __shared__ float smf[];
    const int bm = blockIdx.y;
    const bool is_k = blockIdx.x < 8;
    const int bn = blockIdx.x & 7;

    float acc[4][4][4];
    gemm_core(xs, is_k ? wk : wv, bm, bn, smf, acc);

    const int tid = threadIdx.x, lane = tid & 31, wid = tid >> 5;
    const int warp_m = (wid >> 2) * 64;
    const int warp_n = (wid & 3) * 32;
    const int g = lane >> 2, tig = lane & 3;

    if (is_k) {
        float* red = smf + 8192;   // stage-1 smem; last panel reads stage 0
#pragma unroll
        for (int i = 0; i < 4; i++) {
#pragma unroll
            for (int half = 0; half < 2; half++) {
                float s = 0.f;
#pragma unroll
                for (int j = 0; j < 4; j++) {
                    float x0 = acc[i][j][2 * half + 0];
                    float x1 = acc[i][j][2 * half + 1];
                    s += (x0 > 0.f) ? (x0 + 1.f) : expf(x0);
                    s += (x1 > 0.f) ? (x1 + 1.f) : expf(x1);
                }
                s += __shfl_xor_sync(0xFFFFFFFFu, s, 1);
                s += __shfl_xor_sync(0xFFFFFFFFu, s, 2);
                if (tig == 0)
                    red[(warp_m + 16 * i + 8 * half + g) * 4 + (wid & 3)] = s;
            }
        }
        __syncthreads();
        {
            const int row = tid >> 1, hsel = tid & 1;
            float s = red[row * 4 + 2 * hsel] + red[row * 4 + 2 * hsel + 1];
            g_a[(size_t)(bm * 128 + row) * NH + bn * 2 + hsel] = s;
        }
    } else {
#pragma unroll
        for (int i = 0; i < 4; i++) {
            int row0 = bm * 128 + warp_m + 16 * i + g;
#pragma unroll
            for (int j = 0; j < 4; j++) {
                int colg = bn * 128 + warp_n + 8 * j + 2 * tig;
#pragma unroll
                for (int half = 0; half < 2; half++) {
                    int row = row0 + 8 * half;
                    __half2 o = __floats2half2_rn(acc[i][j][2 * half], acc[i][j][2 * half + 1]);
                    *(__half2*)(g_v_h + (size_t)row * 1024 + colg) = o;
                }
            }
        }
    }
}

// ---------------------------------------------------------------------------
// MLP GEMMs. EPI: 2 = gelu(x+b)->fp16, 3 = x+b->f32
// ---------------------------------------------------------------------------
template<int EPI>
__global__ __launch_bounds__(256, 2)
void gemm_h(const __half* __restrict__ A, const __half* __restrict__ B,
            const float* __restrict__ bias, void* __restrict__ Cv)
{
    extern __shared__ float smf[];
    const int bm = blockIdx.y, bn = blockIdx.x;

    float acc[4][4][4];
    gemm_core(A, B, bm, bn, smf, acc);

    const int tid = threadIdx.x, lane = tid & 31, wid = tid >> 5;
    const int warp_m = (wid >> 2) * 64;
    const int warp_n = (wid & 3) * 32;
    const int g = lane >> 2, tig = lane & 3;

#pragma unroll
    for (int i = 0; i < 4; i++) {
        int row0 = bm * 128 + warp_m + 16 * i + g;
#pragma unroll
        for (int j = 0; j < 4; j++) {
            int colg = bn * 128 + warp_n + 8 * j + 2 * tig;
            float bia0 = bias[colg], bia1 = bias[colg + 1];
#pragma unroll
            for (int half = 0; half < 2; half++) {
                int row = row0 + 8 * half;
                float x0 = acc[i][j][2 * half + 0] + bia0;
                float x1 = acc[i][j][2 * half + 1] + bia1;
                if (EPI == 2) {
                    float t0 = 0.7978845608028654f * (x0 + 0.044715f * x0 * x0 * x0);
                    float t1 = 0.7978845608028654f * (x1 + 0.044715f * x1 * x1 * x1);
                    x0 = 0.5f * x0 * (1.f + tanhf(t0));
                    x1 = 0.5f * x1 * (1.f + tanhf(t1));
                    __half2 o = __floats2half2_rn(x0, x1);
                    *(__half2*)((__half*)Cv + (size_t)row * 1024 + colg) = o;
                } else {
                    float2 o = make_float2(x0, x1);
                    *(float2*)((float*)Cv + (size_t)row * 1024 + colg) = o;
                }
            }
        }
    }
}

// ---------------------------------------------------------------------------
// f32 -> fp16 conversions
__global__ void conv_xs(const float4* __restrict__ src, __half2* __restrict__ dst, int n4)
{
    const int stride = gridDim.x * blockDim.x;
    int i = blockIdx.x * blockDim.x + threadIdx.x;
#pragma unroll
    for (int k = 0; k < 4; k++) {
        int idx = i + k * stride;
        if (idx < n4) {
            float4 v = src[idx];
            dst[2 * idx]     = __floats2half2_rn(v.x, v.y);
            dst[2 * idx + 1] = __floats2half2_rn(v.z, v.w);
        }
    }
}

__global__ void conv_w(const float4* __restrict__ s0, __half2* __restrict__ d0,
                       const float4* __restrict__ s1, __half2* __restrict__ d1,
                       const float4* __restrict__ s2, __half2* __restrict__ d2,
                       const float4* __restrict__ s3, __half2* __restrict__ d3)
{
    const int SEG = 262144;
    const int stride = gridDim.x * blockDim.x;
    int i = blockIdx.x * blockDim.x + threadIdx.x;
#pragma unroll
    for (int k = 0; k < 4; k++) {
        int idx = i + k * stride;
        if (idx >= 4 * SEG) continue;
        const float4* s; __half2* d;
        int seg = idx >> 18, off = idx & (SEG - 1);
        if (seg == 0) { s = s0; d = d0; }
        else if (seg == 1) { s = s1; d = d1; }
        else if (seg == 2) { s = s2; d = d2; }
        else { s = s3; d = d3; }
        float4 v = s[off];
        d[2 * off]     = __floats2half2_rn(v.x, v.y);
        d[2 * off + 1] = __floats2half2_rn(v.z, v.w);
    }
}

// ---- chunked scans: NC=128 chunks of CH=64 steps ----
// pass1: per-chunk sums of a*v (4-way split accumulators) + per-chunk sums of a
__global__ void scan_pass1()
{
    const int c = blockIdx.x, h = blockIdx.y, v = threadIdx.x;
    __shared__ float a_s[CH];
    __shared__ float wsum[2];
    a_s[v] = g_a[(c * CH + v) * NH + h];
    __syncthreads();

    float s = a_s[v];
#pragma unroll
    for (int off = 16; off > 0; off >>= 1)
        s += __shfl_xor_sync(0xFFFFFFFFu, s, off);
    if ((v & 31) == 0) wsum[v >> 5] = s;

    const int hv = h * DH + v;
    const __half* vp = g_v_h + (size_t)c * CH * NN + hv;
    float a0 = 0.f, a1 = 0.f, a2 = 0.f, a3 = 0.f;
#pragma unroll
    for (int t = 0; t < CH; t += 4) {
        a0 = fmaf(a_s[t + 0], __half2float(vp[(size_t)(t + 0) * NN]), a0);
        a1 = fmaf(a_s[t + 1], __half2float(vp[(size_t)(t + 1) * NN]), a1);
        a2 = fmaf(a_s[t + 2], __half2float(vp[(size_t)(t + 2) * NN]), a2);
        a3 = fmaf(a_s[t + 3], __half2float(vp[(size_t)(t + 3) * NN]), a3);
    }
    g_pav[c * NN + hv] = (a0 + a1) + (a2 + a3);

    __syncthreads();
    if (v == 0) g_pa[c * NH + h] = wsum[0] + wsum[1];
}

// exclusive scan over chunks of per-chunk a sums (tiny)
__global__ void scan_pass2a()
{
    const int h = threadIdx.x;
    if (h >= NH) return;
    float acc = 0.f;
    for (int c = 0; c < NC; c++) {
        float x = g_pa[c * NH + h];
        g_basea[c * NH + h] = acc;
        acc += x;
    }
}

// exclusive scan of pav over chunks: one block of 128 threads per hv
__global__ void scan_pass2c()
{
    const int hv = blockIdx.x, t = threadIdx.x;
    __shared__ float s[NC];
    float orig = g_pav[t * NN + hv];
    s[t] = orig;
    __syncthreads();
#pragma unroll
    for (int off = 1; off < NC; off <<= 1) {
        float x = (t >= off) ? s[t - off] : 0.f;
        __syncthreads();
        s[t] += x;
        __syncthreads();
    }
    g_bav[t * NN + hv] = s[t] - orig;
}

// pass3: within-chunk scan + normalize -> fp16 attn
__global__ void scan_pass3()
{
    const int c = blockIdx.x, h = blockIdx.y, v = threadIdx.x;
    __shared__ float a_s[CH];
    __shared__ float sc[CH];
    a_s[v] = g_a[(c * CH + v) * NH + h];
    sc[v] = a_s[v];
    __syncthreads();
#pragma unroll
    for (int off = 1; off < CH; off <<= 1) {
        float x = (v >= off) ? sc[v - off] : 0.f;
        __syncthreads();
        sc[v] += x;
        __syncthreads();
    }
    __shared__ float inv_s[CH];
    inv_s[v] = 1.0f / (g_basea[c * NH + h] + sc[v]);
    __syncthreads();

    const int hv = h * DH + v;
    float acc = g_bav[c * NN + hv];
#pragma unroll 4
    for (int t = 0; t < CH; t++) {
        acc = fmaf(a_s[t], __half2float(g_v_h[(size_t)(c * CH + t) * NN + hv]), acc);
        g_attn_h[(size_t)(c * CH + t) * NN + hv] = __float2half_rn(acc * inv_s[t]);
    }
}

// ---------------------------------------------------------------------------
extern "C" void kernel_launch(void* const* d_in, const int* in_sizes, int n_in,
                              void* d_out, int out_size)
{
    const float* xs = (const float*)d_in[0];
    // d_in[1] = wq: unused (query factor cancels in sq/zq)
    const float* wk = (const float*)d_in[2];
    const float* wv = (const float*)d_in[3];
    const float* w1 = (const float*)d_in[4];
    const float* b1 = (const float*)d_in[5];
    const float* w2 = (const float*)d_in[6];
    const float* b2 = (const float*)d_in[7];
    float* out = (float*)d_out;

    __half *xs_h, *wk_h, *wv_h, *w1_h, *w2_h, *attn_h, *h1_h;
    cudaGetSymbolAddress((void**)&xs_h, g_xs_h);
    cudaGetSymbolAddress((void**)&wk_h, g_wk_h);
    cudaGetSymbolAddress((void**)&wv_h, g_wv_h);
    cudaGetSymbolAddress((void**)&w1_h, g_w1_h);
    cudaGetSymbolAddress((void**)&w2_h, g_w2_h);
    cudaGetSymbolAddress((void**)&attn_h, g_attn_h);
    cudaGetSymbolAddress((void**)&h1_h, g_h1_h);

    cudaFuncSetAttribute(gemm_kv,   cudaFuncAttributeMaxDynamicSharedMemorySize, SMEM_BYTES);
    cudaFuncSetAttribute(gemm_h<2>, cudaFuncAttributeMaxDynamicSharedMemorySize, SMEM_BYTES);
    cudaFuncSetAttribute(gemm_h<3>, cudaFuncAttributeMaxDynamicSharedMemorySize, SMEM_BYTES);

    {
        int n4 = SEQ * DM / 4;
        conv_xs<<<n4 / (256 * 4), 256>>>((const float4*)xs, (__half2*)xs_h, n4);
        conv_w<<<(4 * 262144) / (256 * 4), 256>>>(
            (const float4*)wk, (__half2*)wk_h, (const float4*)wv, (__half2*)wv_h,
            (const float4*)w1, (__half2*)w1_h, (const float4*)w2, (__half2*)w2_h);
    }

    // fused k+v projection (one launch)
    gemm_kv<<<dim3(16, 64), 256, SMEM_BYTES>>>(xs_h, wk_h, wv_h);

    // linear-attention chunked scan
    scan_pass1<<<dim3(NC, NH), CH>>>();
    scan_pass2a<<<1, 32>>>();
    scan_pass2c<<<NN, NC>>>();
    scan_pass3<<<dim3(NC, NH), CH>>>();

    // MLP
    gemm_h<2><<<dim3(8, 64), 256, SMEM_BYTES>>>(attn_h, w1_h, b1, h1_h);
    gemm_h<3><<<dim3(8, 64), 256, SMEM_BYTES>>>(h1_h, w2_h, b2, out);
}

// round 10
// speedup vs baseline: 1.4710x; 1.0293x over previous
#include <cuda_runtime.h>
#include <cuda_fp16.h>
#include <math.h>
#include <stdint.h>

#define SEQ 8192
#define DM 1024
#define NH 16
#define DH 64
#define NN (NH*DH)   // 1024

#define KTOT 1024
#define KSTAGE 64                  // halves per panel row (128B)
#define NSTG 3
#define NKT (KTOT/KSTAGE)          // 16 panels
#define A_BYTES 16384              // 128 rows x 128B
#define B_BYTES 8192               // 64 rows x 128B
#define STG_BYTES (A_BYTES + B_BYTES)   // 24576
#define SMEM_BYTES (NSTG*STG_BYTES)     // 73728

#define NC 128                     // scan chunks
#define CH 64                      // steps per chunk

// ---------------- scratch ----------------
__device__ __half g_xs_h[SEQ * DM];
__device__ __half g_wk_h[NN * DM];
__device__ __half g_wv_h[NN * DM];
__device__ __half g_w1_h[DM * NN];
__device__ __half g_w2_h[NN * DM];
__device__ __half g_attn_h[SEQ * NN];
__device__ __half g_h1_h[SEQ * DM];
__device__ __half g_v_h[SEQ * NN];   // v projection, fp16
__device__ float g_a   [SEQ * NH];
__device__ float g_pa  [NC * NH];    // per-chunk sums of a
__device__ float g_pav [NC * NN];    // per-chunk sums of a*v
__device__ float g_bav [NC * NN];    // exclusive chunk bases of a*v
__device__ float g_basea[NC * NH];   // exclusive chunk bases of a

__device__ __forceinline__ uint32_t smem_u32(const void* p) {
    uint32_t a;
    asm("{ .reg .u64 t; cvta.to.shared.u64 t, %1; cvt.u32.u64 %0, t; }" : "=r"(a) : "l"(p));
    return a;
}

// one stage: A = 4 x 16B, B = 2 x 16B cp.async per thread
__device__ __forceinline__ void load_stage(uint32_t sb, int s, int kt,
                                           const __half* gA, const __half* gB,
                                           const uint32_t* doffA, const uint32_t* doffB)
{
    const uint32_t ab = sb + s * STG_BYTES;
    const uint32_t bb = ab + A_BYTES;
    const __half* a = gA + kt * KSTAGE;
    const __half* b = gB + kt * KSTAGE;
#pragma unroll
    for (int i = 0; i < 4; i++)
        asm volatile("cp.async.cg.shared.global [%0], [%1], 16;"
                     :: "r"(ab + doffA[i]), "l"(a + i * 8) : "memory");
#pragma unroll
    for (int i = 0; i < 2; i++)
        asm volatile("cp.async.cg.shared.global [%0], [%1], 16;"
                     :: "r"(bb + doffB[i]), "l"(b + i * 8) : "memory");
    asm volatile("cp.async.commit_group;" ::: "memory");
}

// ---------------------------------------------------------------------------
// GEMM core: 128x64 CTA tile, 8 warps (4x2) of 32x32, cp.async 3-stage,
// ldmatrix + m16n8k16 fp16 -> f32. Occupancy 3 (regs ~75, smem 72KB).
// acc[i][j]: i = A 16-row block (0..1), j = B 8-col block (0..3).
// ---------------------------------------------------------------------------
__device__ __forceinline__ void gemm_core(const __half* __restrict__ A,
                                          const __half* __restrict__ B,
                                          int bm, int bn, float* smf,
                                          float (&acc)[2][4][4])
{
    const uint32_t sb = smem_u32(smf);
    const int tid = threadIdx.x, lane = tid & 31, wid = tid >> 5;
    const int warp_m = (wid >> 1) * 32;
    const int warp_n = (wid & 1) * 32;

    // A staging: thread -> row tid>>1, 16B chunks (tid&1)*4 .. +3
    const int arow = tid >> 1;
    const int acc0 = (tid & 1) * 4;
    const __half* gA = A + (size_t)(bm * 128 + arow) * KTOT + acc0 * 8;
    uint32_t doffA[4];
#pragma unroll
    for (int i = 0; i < 4; i++)
        doffA[i] = arow * 128 + (((acc0 + i) ^ (arow & 7)) << 4);

    // B staging: thread -> row tid>>2, 16B chunks (tid&3)*2 .. +1
    const int brow = tid >> 2;
    const int bcc0 = (tid & 3) * 2;
    const __half* gB = B + (size_t)(bn * 64 + brow) * KTOT + bcc0 * 8;
    uint32_t doffB[2];
#pragma unroll
    for (int i = 0; i < 2; i++)
        doffB[i] = brow * 128 + (((bcc0 + i) ^ (brow & 7)) << 4);

    const int rbase = (lane & 7) + ((lane >> 3) & 1) * 8;
    const int klane = lane >> 4;
    const int rA_base = warp_m + rbase;
    const int rB_base = warp_n + rbase;

#pragma unroll
    for (int i = 0; i < 2; i++)
#pragma unroll
        for (int j = 0; j < 4; j++)
#pragma unroll
            for (int q = 0; q < 4; q++) acc[i][j][q] = 0.f;

    load_stage(sb, 0, 0, gA, gB, doffA, doffB);
    load_stage(sb, 1, 1, gA, gB, doffA, doffB);

    for (int kt = 0; kt < NKT; kt++) {
        if (kt + 1 < NKT) asm volatile("cp.async.wait_group 1;" ::: "memory");
        else              asm volatile("cp.async.wait_group 0;" ::: "memory");
        __syncthreads();
        if (kt + 2 < NKT) load_stage(sb, (kt + 2) % NSTG, kt + 2, gA, gB, doffA, doffB);

        const uint32_t ab = sb + (kt % NSTG) * STG_BYTES;
        const uint32_t bb = ab + A_BYTES;

#pragma unroll
        for (int kg = 0; kg < 4; kg++) {
            const int kc = 2 * kg + klane;
            uint32_t bfr[8];
#pragma unroll
            for (int p = 0; p < 2; p++) {
                const int row = rB_base + 16 * p;
                uint32_t addr = bb + (uint32_t)row * 128 + (uint32_t)((kc ^ (row & 7)) << 4);
                asm volatile("ldmatrix.sync.aligned.m8n8.x4.shared.b16 {%0,%1,%2,%3}, [%4];"
                    : "=r"(bfr[4*p]), "=r"(bfr[4*p+1]), "=r"(bfr[4*p+2]), "=r"(bfr[4*p+3])
                    : "r"(addr));
            }
#pragma unroll
            for (int i = 0; i < 2; i++) {
                const int row = rA_base + 16 * i;
                uint32_t af[4];
                uint32_t addr = ab + (uint32_t)row * 128 + (uint32_t)((kc ^ (row & 7)) << 4);
                asm volatile("ldmatrix.sync.aligned.m8n8.x4.shared.b16 {%0,%1,%2,%3}, [%4];"
                    : "=r"(af[0]), "=r"(af[1]), "=r"(af[2]), "=r"(af[3]) : "r"(addr));
#pragma unroll
                for (int j = 0; j < 4; j++) {
                    const int bi = (j >> 1) * 4 + (j & 1);
                    asm volatile(
                        "mma.sync.aligned.m16n8k16.row.col.f32.f16.f16.f32 "
                        "{%0,%1,%2,%3}, {%4,%5,%6,%7}, {%8,%9}, {%0,%1,%2,%3};"
                        : "+f"(acc[i][j][0]), "+f"(acc[i][j][1]),
                          "+f"(acc[i][j][2]), "+f"(acc[i][j][3])
                        : "r"(af[0]), "r"(af[1]), "r"(af[2]), "r"(af[3]),
                          "r"(bfr[bi]), "r"(bfr[bi + 2]));
                }
            }
        }
    }
}

// ---------------------------------------------------------------------------
// Fused K+V projection: grid (32, 64). bx<16 -> k-proj CTA covering head bx
// (elu+1, per-head reduce into g_a); bx>=16 -> v-proj -> fp16.
// ---------------------------------------------------------------------------
__global__ __launch_bounds__(256, 3)
void gemm_kv(const __half* __restrict__ xs, const __half* __restrict__ wk,
             const __half* __restrict__ wv)
{
    extern __shared__ float smf[];
    const int bm = blockIdx.y;
    const bool is_k = blockIdx.x < 16;
    const int bn = blockIdx.x & 15;

    float acc[2][4][4];
    gemm_core(xs, is_k ? wk : wv, bm, bn, smf, acc);

    const int tid = threadIdx.x, lane = tid & 31, wid = tid >> 5;
    const int warp_m = (wid >> 1) * 32;
    const int warp_n = (wid & 1) * 32;
    const int g = lane >> 2, tig = lane & 3;

    if (is_k) {
        // CTA's 64 cols = head bn. Warp sums its 32 cols; combine 2 halves in smem.
        // red in stage-1 smem region (last panel kt=15 uses stage 0).
        float* red = smf + (STG_BYTES / 4);   // [128 rows][2]
#pragma unroll
        for (int i = 0; i < 2; i++) {
#pragma unroll
            for (int half = 0; half < 2; half++) {
                float s = 0.f;
#pragma unroll
                for (int j = 0; j < 4; j++) {
                    float x0 = acc[i][j][2 * half + 0];
                    float x1 = acc[i][j][2 * half + 1];
                    s += (x0 > 0.f) ? (x0 + 1.f) : expf(x0);
                    s += (x1 > 0.f) ? (x1 + 1.f) : expf(x1);
                }
                s += __shfl_xor_sync(0xFFFFFFFFu, s, 1);
                s += __shfl_xor_sync(0xFFFFFFFFu, s, 2);
                if (tig == 0)
                    red[(warp_m + 16 * i + 8 * half + g) * 2 + (wid & 1)] = s;
            }
        }
        __syncthreads();
        if (tid < 128) {
            float s = red[tid * 2] + red[tid * 2 + 1];
            g_a[(size_t)(bm * 128 + tid) * NH + bn] = s;
        }
    } else {
#pragma unroll
        for (int i = 0; i < 2; i++) {
            int row0 = bm * 128 + warp_m + 16 * i + g;
#pragma unroll
            for (int j = 0; j < 4; j++) {
                int colg = bn * 64 + warp_n + 8 * j + 2 * tig;
#pragma unroll
                for (int half = 0; half < 2; half++) {
                    int row = row0 + 8 * half;
                    __half2 o = __floats2half2_rn(acc[i][j][2 * half], acc[i][j][2 * half + 1]);
                    *(__half2*)(g_v_h + (size_t)row * 1024 + colg) = o;
                }
            }
        }
    }
}

// ---------------------------------------------------------------------------
// MLP GEMMs. EPI: 2 = gelu(x+b)->fp16, 3 = x+b->f32
// ---------------------------------------------------------------------------
template<int EPI>
__global__ __launch_bounds__(256, 3)
void gemm_h(const __half* __restrict__ A, const __half* __restrict__ B,
            const float* __restrict__ bias, void* __restrict__ Cv)
{
    extern __shared__ float smf[];
    const int bm = blockIdx.y, bn = blockIdx.x;

    float acc[2][4][4];
    gemm_core(A, B, bm, bn, smf, acc);

    const int tid = threadIdx.x, lane = tid & 31, wid = tid >> 5;
    const int warp_m = (wid >> 1) * 32;
    const int warp_n = (wid & 1) * 32;
    const int g = lane >> 2, tig = lane & 3;

#pragma unroll
    for (int i = 0; i < 2; i++) {
        int row0 = bm * 128 + warp_m + 16 * i + g;
#pragma unroll
        for (int j = 0; j < 4; j++) {
            int colg = bn * 64 + warp_n + 8 * j + 2 * tig;
            float bia0 = bias[colg], bia1 = bias[colg + 1];
#pragma unroll
            for (int half = 0; half < 2; half++) {
                int row = row0 + 8 * half;
                float x0 = acc[i][j][2 * half + 0] + bia0;
                float x1 = acc[i][j][2 * half + 1] + bia1;
                if (EPI == 2) {
                    float t0 = 0.7978845608028654f * (x0 + 0.044715f * x0 * x0 * x0);
                    float t1 = 0.7978845608028654f * (x1 + 0.044715f * x1 * x1 * x1);
                    x0 = 0.5f * x0 * (1.f + tanhf(t0));
                    x1 = 0.5f * x1 * (1.f + tanhf(t1));
                    __half2 o = __floats2half2_rn(x0, x1);
                    *(__half2*)((__half*)Cv + (size_t)row * 1024 + colg) = o;
                } else {
                    float2 o = make_float2(x0, x1);
                    *(float2*)((float*)Cv + (size_t)row * 1024 + colg) = o;
                }
            }
        }
    }
}

// ---------------------------------------------------------------------------
// f32 -> fp16 conversions
__global__ void conv_xs(const float4* __restrict__ src, __half2* __restrict__ dst, int n4)
{
    const int stride = gridDim.x * blockDim.x;
    int i = blockIdx.x * blockDim.x + threadIdx.x;
#pragma unroll
    for (int k = 0; k < 4; k++) {
        int idx = i + k * stride;
        if (idx < n4) {
            float4 v = src[idx];
            dst[2 * idx]     = __floats2half2_rn(v.x, v.y);
            dst[2 * idx + 1] = __floats2half2_rn(v.z, v.w);
        }
    }
}

__global__ void conv_w(const float4* __restrict__ s0, __half2* __restrict__ d0,
                       const float4* __restrict__ s1, __half2* __restrict__ d1,
                       const float4* __restrict__ s2, __half2* __restrict__ d2,
                       const float4* __restrict__ s3, __half2* __restrict__ d3)
{
    const int SEG = 262144;
    const int stride = gridDim.x * blockDim.x;
    int i = blockIdx.x * blockDim.x + threadIdx.x;
#pragma unroll
    for (int k = 0; k < 4; k++) {
        int idx = i + k * stride;
        if (idx >= 4 * SEG) continue;
        const float4* s; __half2* d;
        int seg = idx >> 18, off = idx & (SEG - 1);
        if (seg == 0) { s = s0; d = d0; }
        else if (seg == 1) { s = s1; d = d1; }
        else if (seg == 2) { s = s2; d = d2; }
        else { s = s3; d = d3; }
        float4 v = s[off];
        d[2 * off]     = __floats2half2_rn(v.x, v.y);
        d[2 * off + 1] = __floats2half2_rn(v.z, v.w);
    }
}

// ---- chunked scans: NC=128 chunks of CH=64 steps ----
__global__ void scan_pass1()
{
    const int c = blockIdx.x, h = blockIdx.y, v = threadIdx.x;
    __shared__ float a_s[CH];
    __shared__ float wsum[2];
    a_s[v] = g_a[(c * CH + v) * NH + h];
    __syncthreads();

    float s = a_s[v];
#pragma unroll
    for (int off = 16; off > 0; off >>= 1)
        s += __shfl_xor_sync(0xFFFFFFFFu, s, off);
    if ((v & 31) == 0) wsum[v >> 5] = s;

    const int hv = h * DH + v;
    const __half* vp = g_v_h + (size_t)c * CH * NN + hv;
    float a0 = 0.f, a1 = 0.f, a2 = 0.f, a3 = 0.f;
#pragma unroll
    for (int t = 0; t < CH; t += 4) {
        a0 = fmaf(a_s[t + 0], __half2float(vp[(size_t)(t + 0) * NN]), a0);
        a1 = fmaf(a_s[t + 1], __half2float(vp[(size_t)(t + 1) * NN]), a1);
        a2 = fmaf(a_s[t + 2], __half2float(vp[(size_t)(t + 2) * NN]), a2);
        a3 = fmaf(a_s[t + 3], __half2float(vp[(size_t)(t + 3) * NN]), a3);
    }
    g_pav[c * NN + hv] = (a0 + a1) + (a2 + a3);

    __syncthreads();
    if (v == 0) g_pa[c * NH + h] = wsum[0] + wsum[1];
}

__global__ void scan_pass2a()
{
    const int h = threadIdx.x;
    if (h >= NH) return;
    float acc = 0.f;
    for (int c = 0; c < NC; c++) {
        float x = g_pa[c * NH + h];
        g_basea[c * NH + h] = acc;
        acc += x;
    }
}

__global__ void scan_pass2c()
{
    const int hv = blockIdx.x, t = threadIdx.x;
    __shared__ float s[NC];
    float orig = g_pav[t * NN + hv];
    s[t] = orig;
    __syncthreads();
#pragma unroll
    for (int off = 1; off < NC; off <<= 1) {
        float x = (t >= off) ? s[t - off] : 0.f;
        __syncthreads();
        s[t] += x;
        __syncthreads();
    }
    g_bav[t * NN + hv] = s[t] - orig;
}

__global__ void scan_pass3()
{
    const int c = blockIdx.x, h = blockIdx.y, v = threadIdx.x;
    __shared__ float a_s[CH];
    __shared__ float sc[CH];
    a_s[v] = g_a[(c * CH + v) * NH + h];
    sc[v] = a_s[v];
    __syncthreads();
#pragma unroll
    for (int off = 1; off < CH; off <<= 1) {
        float x = (v >= off) ? sc[v - off] : 0.f;
        __syncthreads();
        sc[v] += x;
        __syncthreads();
    }
    __shared__ float inv_s[CH];
    inv_s[v] = 1.0f / (g_basea[c * NH + h] + sc[v]);
    __syncthreads();

    const int hv = h * DH + v;
    float acc = g_bav[c * NN + hv];
#pragma unroll 4
    for (int t = 0; t < CH; t++) {
        acc = fmaf(a_s[t], __half2float(g_v_h[(size_t)(c * CH + t) * NN + hv]), acc);
        g_attn_h[(size_t)(c * CH + t) * NN + hv] = __float2half_rn(acc * inv_s[t]);
    }
}

// ---------------------------------------------------------------------------
extern "C" void kernel_launch(void* const* d_in, const int* in_sizes, int n_in,
                              void* d_out, int out_size)
{
    const float* xs = (const float*)d_in[0];
    // d_in[1] = wq: unused (query factor cancels in sq/zq)
    const float* wk = (const float*)d_in[2];
    const float* wv = (const float*)d_in[3];
    const float* w1 = (const float*)d_in[4];
    const float* b1 = (const float*)d_in[5];
    const float* w2 = (const float*)d_in[6];
    const float* b2 = (const float*)d_in[7];
    float* out = (float*)d_out;

    __half *xs_h, *wk_h, *wv_h, *w1_h, *w2_h, *attn_h, *h1_h;
    cudaGetSymbolAddress((void**)&xs_h, g_xs_h);
    cudaGetSymbolAddress((void**)&wk_h, g_wk_h);
    cudaGetSymbolAddress((void**)&wv_h, g_wv_h);
    cudaGetSymbolAddress((void**)&w1_h, g_w1_h);
    cudaGetSymbolAddress((void**)&w2_h, g_w2_h);
    cudaGetSymbolAddress((void**)&attn_h, g_attn_h);
    cudaGetSymbolAddress((void**)&h1_h, g_h1_h);

    cudaFuncSetAttribute(gemm_kv,   cudaFuncAttributeMaxDynamicSharedMemorySize, SMEM_BYTES);
    cudaFuncSetAttribute(gemm_h<2>, cudaFuncAttributeMaxDynamicSharedMemorySize, SMEM_BYTES);
    cudaFuncSetAttribute(gemm_h<3>, cudaFuncAttributeMaxDynamicSharedMemorySize, SMEM_BYTES);

    {
        int n4 = SEQ * DM / 4;
        conv_xs<<<n4 / (256 * 4), 256>>>((const float4*)xs, (__half2*)xs_h, n4);
        conv_w<<<(4 * 262144) / (256 * 4), 256>>>(
            (const float4*)wk, (__half2*)wk_h, (const float4*)wv, (__half2*)wv_h,
            (const float4*)w1, (__half2*)w1_h, (const float4*)w2, (__half2*)w2_h);
    }

    // fused k+v projection (one launch, 128x64 tiles)
    gemm_kv<<<dim3(32, 64), 256, SMEM_BYTES>>>(xs_h, wk_h, wv_h);

    // linear-attention chunked scan
    scan_pass1<<<dim3(NC, NH), CH>>>();
    scan_pass2a<<<1, 32>>>();
    scan_pass2c<<<NN, NC>>>();
    scan_pass3<<<dim3(NC, NH), CH>>>();

    // MLP (128x64 tiles)
    gemm_h<2><<<dim3(16, 64), 256, SMEM_BYTES>>>(attn_h, w1_h, b1, h1_h);
    gemm_h<3><<<dim3(16, 64), 256, SMEM_BYTES>>>(h1_h, w2_h, b2, out);
}

// round 11
// speedup vs baseline: 1.4989x; 1.0190x over previous
#include <cuda_runtime.h>
#include <cuda_fp16.h>
#include <math.h>
#include <stdint.h>

#define SEQ 8192
#define DM 1024
#define NH 16
#define DH 64
#define NN (NH*DH)   // 1024

#define KTOT 1024
#define KSTAGE 64                  // halves per panel row (128B)
#define NSTG 3
#define NKT (KTOT/KSTAGE)          // 16 panels
#define A_BYTES 32768              // 256 rows x 128B
#define B_BYTES 16384              // 128 rows x 128B
#define STG_BYTES (A_BYTES + B_BYTES)   // 49152
#define SMEM_BYTES (NSTG*STG_BYTES)     // 147456

#define NC 128                     // scan chunks
#define CH 64                      // steps per chunk

// ---------------- scratch ----------------
__device__ __half g_xs_h[SEQ * DM];
__device__ __half g_wk_h[NN * DM];
__device__ __half g_wv_h[NN * DM];
__device__ __half g_w1_h[DM * NN];
__device__ __half g_w2_h[NN * DM];
__device__ __half g_attn_h[SEQ * NN];
__device__ __half g_h1_h[SEQ * DM];
__device__ __half g_v_h[SEQ * NN];   // v projection, fp16
__device__ float g_a   [SEQ * NH];
__device__ float g_pa  [NC * NH];    // per-chunk sums of a
__device__ float g_pav [NC * NN];    // per-chunk sums of a*v
__device__ float g_bav [NC * NN];    // exclusive chunk bases of a*v
__device__ float g_basea[NC * NH];   // exclusive chunk bases of a

__device__ __forceinline__ uint32_t smem_u32(const void* p) {
    uint32_t a;
    asm("{ .reg .u64 t; cvta.to.shared.u64 t, %1; cvt.u32.u64 %0, t; }" : "=r"(a) : "l"(p));
    return a;
}

// one stage: A = 4 x 16B, B = 2 x 16B cp.async per thread (512 threads, 48KB)
__device__ __forceinline__ void load_stage(uint32_t sb, int s, int kt,
                                           const __half* gA, const __half* gB,
                                           const uint32_t* doffA, const uint32_t* doffB)
{
    const uint32_t ab = sb + s * STG_BYTES;
    const uint32_t bb = ab + A_BYTES;
    const __half* a = gA + kt * KSTAGE;
    const __half* b = gB + kt * KSTAGE;
#pragma unroll
    for (int i = 0; i < 4; i++)
        asm volatile("cp.async.cg.shared.global [%0], [%1], 16;"
                     :: "r"(ab + doffA[i]), "l"(a + i * 8) : "memory");
#pragma unroll
    for (int i = 0; i < 2; i++)
        asm volatile("cp.async.cg.shared.global [%0], [%1], 16;"
                     :: "r"(bb + doffB[i]), "l"(b + i * 8) : "memory");
    asm volatile("cp.async.commit_group;" ::: "memory");
}

// ---------------------------------------------------------------------------
// GEMM core: 256x128 CTA tile, 16 warps (4x4) of 64x32 (R6-proven inner loop),
// cp.async 3-stage, ldmatrix, m16n8k16 fp16 -> f32. Occ 1 (smem 144KB).
// ---------------------------------------------------------------------------
__device__ __forceinline__ void gemm_core(const __half* __restrict__ A,
                                          const __half* __restrict__ B,
                                          int bm, int bn, float* smf,
                                          float (&acc)[4][4][4])
{
    const uint32_t sb = smem_u32(smf);
    const int tid = threadIdx.x, lane = tid & 31, wid = tid >> 5;
    const int warp_m = (wid >> 2) * 64;   // 0,64,128,192
    const int warp_n = (wid & 3) * 32;    // 0,32,64,96

    // A staging: thread -> row tid>>1 (0..255), 16B chunks (tid&1)*4 .. +3
    const int arow = tid >> 1;
    const int ac0 = (tid & 1) * 4;
    const __half* gA = A + (size_t)(bm * 256 + arow) * KTOT + ac0 * 8;
    uint32_t doffA[4];
#pragma unroll
    for (int i = 0; i < 4; i++)
        doffA[i] = arow * 128 + (((ac0 + i) ^ (arow & 7)) << 4);

    // B staging: thread -> row tid>>2 (0..127), 16B chunks (tid&3)*2 .. +1
    const int brow = tid >> 2;
    const int bc0 = (tid & 3) * 2;
    const __half* gB = B + (size_t)(bn * 128 + brow) * KTOT + bc0 * 8;
    uint32_t doffB[2];
#pragma unroll
    for (int i = 0; i < 2; i++)
        doffB[i] = brow * 128 + (((bc0 + i) ^ (brow & 7)) << 4);

    const int rbase = (lane & 7) + ((lane >> 3) & 1) * 8;
    const int klane = lane >> 4;
    const int rA_base = warp_m + rbase;
    const int rB_base = warp_n + rbase;

#pragma unroll
    for (int i = 0; i < 4; i++)
#pragma unroll
        for (int j = 0; j < 4; j++)
#pragma unroll
            for (int q = 0; q < 4; q++) acc[i][j][q] = 0.f;

    load_stage(sb, 0, 0, gA, gB, doffA, doffB);
    load_stage(sb, 1, 1, gA, gB, doffA, doffB);

    for (int kt = 0; kt < NKT; kt++) {
        if (kt + 1 < NKT) asm volatile("cp.async.wait_group 1;" ::: "memory");
        else              asm volatile("cp.async.wait_group 0;" ::: "memory");
        __syncthreads();
        if (kt + 2 < NKT) load_stage(sb, (kt + 2) % NSTG, kt + 2, gA, gB, doffA, doffB);

        const uint32_t ab = sb + (kt % NSTG) * STG_BYTES;
        const uint32_t bb = ab + A_BYTES;

#pragma unroll
        for (int kg = 0; kg < 4; kg++) {
            const int kc = 2 * kg + klane;
            uint32_t bfr[8];
#pragma unroll
            for (int p = 0; p < 2; p++) {
                const int row = rB_base + 16 * p;
                uint32_t addr = bb + (uint32_t)row * 128 + (uint32_t)((kc ^ (row & 7)) << 4);
                asm volatile("ldmatrix.sync.aligned.m8n8.x4.shared.b16 {%0,%1,%2,%3}, [%4];"
                    : "=r"(bfr[4*p]), "=r"(bfr[4*p+1]), "=r"(bfr[4*p+2]), "=r"(bfr[4*p+3])
                    : "r"(addr));
            }
#pragma unroll
            for (int i = 0; i < 4; i++) {
                const int row = rA_base + 16 * i;
                uint32_t af[4];
                uint32_t addr = ab + (uint32_t)row * 128 + (uint32_t)((kc ^ (row & 7)) << 4);
                asm volatile("ldmatrix.sync.aligned.m8n8.x4.shared.b16 {%0,%1,%2,%3}, [%4];"
                    : "=r"(af[0]), "=r"(af[1]), "=r"(af[2]), "=r"(af[3]) : "r"(addr));
#pragma unroll
                for (int j = 0; j < 4; j++) {
                    const int bi = (j >> 1) * 4 + (j & 1);
                    asm volatile(
                        "mma.sync.aligned.m16n8k16.row.col.f32.f16.f16.f32 "
                        "{%0,%1,%2,%3}, {%4,%5,%6,%7}, {%8,%9}, {%0,%1,%2,%3};"
                        : "+f"(acc[i][j][0]), "+f"(acc[i][j][1]),
                          "+f"(acc[i][j][2]), "+f"(acc[i][j][3])
                        : "r"(af[0]), "r"(af[1]), "r"(af[2]), "r"(af[3]),
                          "r"(bfr[bi]), "r"(bfr[bi + 2]));
                }
            }
        }
    }
}

// ---------------------------------------------------------------------------
// Fused K+V projection: grid (16, 32). bx<8 -> k-proj (elu+1, per-head reduce
// into g_a); bx>=8 -> v-proj -> fp16. CTA covers 256 rows x 128 cols (2 heads).
// ---------------------------------------------------------------------------
__global__ __launch_bounds__(512, 1)
void gemm_kv(const __half* __restrict__ xs, const __half* __restrict__ wk,
             const __half* __restrict__ wv)
{
    extern __shared__ float smf[];
    const int bm = blockIdx.y;
    const bool is_k = blockIdx.x < 8;
    const int bn = blockIdx.x & 7;

    float acc[4][4][4];
    gemm_core(xs, is_k ? wk : wv, bm, bn, smf, acc);

    const int tid = threadIdx.x, lane = tid & 31, wid = tid >> 5;
    const int warp_m = (wid >> 2) * 64;
    const int warp_n = (wid & 3) * 32;
    const int g = lane >> 2, tig = lane & 3;

    if (is_k) {
        // After the loop all cp.async groups are drained -> smem reusable.
        float* red = smf + (STG_BYTES / 4);   // [256 rows][4 warp_n groups]
#pragma unroll
        for (int i = 0; i < 4; i++) {
#pragma unroll
            for (int half = 0; half < 2; half++) {
                float s = 0.f;
#pragma unroll
                for (int j = 0; j < 4; j++) {
                    float x0 = acc[i][j][2 * half + 0];
                    float x1 = acc[i][j][2 * half + 1];
                    s += (x0 > 0.f) ? (x0 + 1.f) : expf(x0);
                    s += (x1 > 0.f) ? (x1 + 1.f) : expf(x1);
                }
                s += __shfl_xor_sync(0xFFFFFFFFu, s, 1);
                s += __shfl_xor_sync(0xFFFFFFFFu, s, 2);
                if (tig == 0)
                    red[(warp_m + 16 * i + 8 * half + g) * 4 + (wid & 3)] = s;
            }
        }
        __syncthreads();
        {
            // 512 threads: row = tid>>1 (0..255), hsel = tid&1
            const int row = tid >> 1, hsel = tid & 1;
            float s = red[row * 4 + 2 * hsel] + red[row * 4 + 2 * hsel + 1];
            g_a[(size_t)(bm * 256 + row) * NH + bn * 2 + hsel] = s;
        }
    } else {
#pragma unroll
        for (int i = 0; i < 4; i++) {
            int row0 = bm * 256 + warp_m + 16 * i + g;
#pragma unroll
            for (int j = 0; j < 4; j++) {
                int colg = bn * 128 + warp_n + 8 * j + 2 * tig;
#pragma unroll
                for (int half = 0; half < 2; half++) {
                    int row = row0 + 8 * half;
                    __half2 o = __floats2half2_rn(acc[i][j][2 * half], acc[i][j][2 * half + 1]);
                    *(__half2*)(g_v_h + (size_t)row * 1024 + colg) = o;
                }
            }
        }
    }
}

// ---------------------------------------------------------------------------
// MLP GEMMs: grid (8, 32). EPI: 2 = gelu(x+b)->fp16, 3 = x+b->f32
// ---------------------------------------------------------------------------
template<int EPI>
__global__ __launch_bounds__(512, 1)
void gemm_h(const __half* __restrict__ A, const __half* __restrict__ B,
            const float* __restrict__ bias, void* __restrict__ Cv)
{
    extern __shared__ float smf[];
    const int bm = blockIdx.y, bn = blockIdx.x;

    float acc[4][4][4];
    gemm_core(A, B, bm, bn, smf, acc);

    const int tid = threadIdx.x, lane = tid & 31, wid = tid >> 5;
    const int warp_m = (wid >> 2) * 64;
    const int warp_n = (wid & 3) * 32;
    const int g = lane >> 2, tig = lane & 3;

#pragma unroll
    for (int i = 0; i < 4; i++) {
        int row0 = bm * 256 + warp_m + 16 * i + g;
#pragma unroll
        for (int j = 0; j < 4; j++) {
            int colg = bn * 128 + warp_n + 8 * j + 2 * tig;
            float bia0 = bias[colg], bia1 = bias[colg + 1];
#pragma unroll
            for (int half = 0; half < 2; half++) {
                int row = row0 + 8 * half;
                float x0 = acc[i][j][2 * half + 0] + bia0;
                float x1 = acc[i][j][2 * half + 1] + bia1;
                if (EPI == 2) {
                    float t0 = 0.7978845608028654f * (x0 + 0.044715f * x0 * x0 * x0);
                    float t1 = 0.7978845608028654f * (x1 + 0.044715f * x1 * x1 * x1);
                    x0 = 0.5f * x0 * (1.f + tanhf(t0));
                    x1 = 0.5f * x1 * (1.f + tanhf(t1));
                    __half2 o = __floats2half2_rn(x0, x1);
                    *(__half2*)((__half*)Cv + (size_t)row * 1024 + colg) = o;
                } else {
                    float2 o = make_float2(x0, x1);
                    *(float2*)((float*)Cv + (size_t)row * 1024 + colg) = o;
                }
            }
        }
    }
}

// ---------------------------------------------------------------------------
// f32 -> fp16 conversion: one launch for xs (8 segs) + 4 weights (1 seg each).
__global__ void conv_all(const float4* __restrict__ xs, __half2* __restrict__ xs_h,
                         const float4* __restrict__ s0, __half2* __restrict__ d0,
                         const float4* __restrict__ s1, __half2* __restrict__ d1,
                         const float4* __restrict__ s2, __half2* __restrict__ d2,
                         const float4* __restrict__ s3, __half2* __restrict__ d3)
{
    const int SEG = 262144;               // float4s per 1M-float tensor
    const int stride = gridDim.x * blockDim.x;
    int i = blockIdx.x * blockDim.x + threadIdx.x;
#pragma unroll
    for (int k = 0; k < 4; k++) {
        int idx = i + k * stride;
        if (idx >= 12 * SEG) continue;
        const float4* s; __half2* d; int off;
        if (idx < 8 * SEG) { s = xs; d = xs_h; off = idx; }
        else {
            int seg = (idx >> 18) - 8;
            off = idx & (SEG - 1);
            if (seg == 0) { s = s0; d = d0; }
            else if (seg == 1) { s = s1; d = d1; }
            else if (seg == 2) { s = s2; d = d2; }
            else { s = s3; d = d3; }
        }
        float4 v = s[off];
        d[2 * off]     = __floats2half2_rn(v.x, v.y);
        d[2 * off + 1] = __floats2half2_rn(v.z, v.w);
    }
}

// ---- chunked scans: NC=128 chunks of CH=64 steps ----
__global__ void scan_pass1()
{
    const int c = blockIdx.x, h = blockIdx.y, v = threadIdx.x;
    __shared__ float a_s[CH];
    __shared__ float wsum[2];
    a_s[v] = g_a[(c * CH + v) * NH + h];
    __syncthreads();

    float s = a_s[v];
#pragma unroll
    for (int off = 16; off > 0; off >>= 1)
        s += __shfl_xor_sync(0xFFFFFFFFu, s, off);
    if ((v & 31) == 0) wsum[v >> 5] = s;

    const int hv = h * DH + v;
    const __half* vp = g_v_h + (size_t)c * CH * NN + hv;
    float a0 = 0.f, a1 = 0.f, a2 = 0.f, a3 = 0.f;
#pragma unroll
    for (int t = 0; t < CH; t += 4) {
        a0 = fmaf(a_s[t + 0], __half2float(vp[(size_t)(t + 0) * NN]), a0);
        a1 = fmaf(a_s[t + 1], __half2float(vp[(size_t)(t + 1) * NN]), a1);
        a2 = fmaf(a_s[t + 2], __half2float(vp[(size_t)(t + 2) * NN]), a2);
        a3 = fmaf(a_s[t + 3], __half2float(vp[(size_t)(t + 3) * NN]), a3);
    }
    g_pav[c * NN + hv] = (a0 + a1) + (a2 + a3);

    __syncthreads();
    if (v == 0) g_pa[c * NH + h] = wsum[0] + wsum[1];
}

// exclusive chunk scans: pav for all hv; blocks hv<NH also scan pa -> basea
__global__ void scan_pass2c()
{
    const int hv = blockIdx.x, t = threadIdx.x;
    __shared__ float s[NC];
    __shared__ float s2[NC];
    float orig = g_pav[t * NN + hv];
    s[t] = orig;
    const bool do2 = (hv < NH);
    float orig2 = 0.f;
    if (do2) { orig2 = g_pa[t * NH + hv]; s2[t] = orig2; }
    __syncthreads();
#pragma unroll
    for (int off = 1; off < NC; off <<= 1) {
        float x  = (t >= off) ? s[t - off] : 0.f;
        float x2 = (do2 && t >= off) ? s2[t - off] : 0.f;
        __syncthreads();
        s[t] += x;
        if (do2) s2[t] += x2;
        __syncthreads();
    }
    g_bav[t * NN + hv] = s[t] - orig;
    if (do2) g_basea[t * NH + hv] = s2[t] - orig2;
}

__global__ void scan_pass3()
{
    const int c = blockIdx.x, h = blockIdx.y, v = threadIdx.x;
    __shared__ float a_s[CH];
    __shared__ float sc[CH];
    a_s[v] = g_a[(c * CH + v) * NH + h];
    sc[v] = a_s[v];
    __syncthreads();
#pragma unroll
    for (int off = 1; off < CH; off <<= 1) {
        float x = (v >= off) ? sc[v - off] : 0.f;
        __syncthreads();
        sc[v] += x;
        __syncthreads();
    }
    __shared__ float inv_s[CH];
    inv_s[v] = 1.0f / (g_basea[c * NH + h] + sc[v]);
    __syncthreads();

    const int hv = h * DH + v;
    float acc = g_bav[c * NN + hv];
#pragma unroll 4
    for (int t = 0; t < CH; t++) {
        acc = fmaf(a_s[t], __half2float(g_v_h[(size_t)(c * CH + t) * NN + hv]), acc);
        g_attn_h[(size_t)(c * CH + t) * NN + hv] = __float2half_rn(acc * inv_s[t]);
    }
}

// ---------------------------------------------------------------------------
extern "C" void kernel_launch(void* const* d_in, const int* in_sizes, int n_in,
                              void* d_out, int out_size)
{
    const float* xs = (const float*)d_in[0];
    // d_in[1] = wq: unused (query factor cancels in sq/zq)
    const float* wk = (const float*)d_in[2];
    const float* wv = (const float*)d_in[3];
    const float* w1 = (const float*)d_in[4];
    const float* b1 = (const float*)d_in[5];
    const float* w2 = (const float*)d_in[6];
    const float* b2 = (const float*)d_in[7];
    float* out = (float*)d_out;

    __half *xs_h, *wk_h, *wv_h, *w1_h, *w2_h, *attn_h, *h1_h;
    cudaGetSymbolAddress((void**)&xs_h, g_xs_h);
    cudaGetSymbolAddress((void**)&wk_h, g_wk_h);
    cudaGetSymbolAddress((void**)&wv_h, g_wv_h);
    cudaGetSymbolAddress((void**)&w1_h, g_w1_h);
    cudaGetSymbolAddress((void**)&w2_h, g_w2_h);
    cudaGetSymbolAddress((void**)&attn_h, g_attn_h);
    cudaGetSymbolAddress((void**)&h1_h, g_h1_h);

    cudaFuncSetAttribute(gemm_kv,   cudaFuncAttributeMaxDynamicSharedMemorySize, SMEM_BYTES);
    cudaFuncSetAttribute(gemm_h<2>, cudaFuncAttributeMaxDynamicSharedMemorySize, SMEM_BYTES);
    cudaFuncSetAttribute(gemm_h<3>, cudaFuncAttributeMaxDynamicSharedMemorySize, SMEM_BYTES);

    // 1: conversions (one launch)
    conv_all<<<(12 * 262144) / (256 * 4), 256>>>(
        (const float4*)xs, (__half2*)xs_h,
        (const float4*)wk, (__half2*)wk_h, (const float4*)wv, (__half2*)wv_h,
        (const float4*)w1, (__half2*)w1_h, (const float4*)w2, (__half2*)w2_h);

    // 2: fused k+v projection (256x128 tiles)
    gemm_kv<<<dim3(16, 32), 512, SMEM_BYTES>>>(xs_h, wk_h, wv_h);

    // 3-5: linear-attention chunked scan
    scan_pass1<<<dim3(NC, NH), CH>>>();
    scan_pass2c<<<NN, NC>>>();
    scan_pass3<<<dim3(NC, NH), CH>>>();

    // 6-7: MLP (256x128 tiles)
    gemm_h<2><<<dim3(8, 32), 512, SMEM_BYTES>>>(attn_h, w1_h, b1, h1_h);
    gemm_h<3><<<dim3(8, 32), 512, SMEM_BYTES>>>(h1_h, w2_h, b2, out);
}